// round 10
// baseline (speedup 1.0000x reference)
#include <cuda_runtime.h>
#include <cuda_bf16.h>
#include <math.h>

// S4D kernel init via warp-level TF32 mma.sync (baseline PTX, works on the
// harness's compute_103 target -- tcgen05 is NOT available in this build).
//
// out[h, j*128+i] = sum_n Px[n,j]*Qr[n,i] - Py[n,j]*Qi[n,i]
//   = D[j,i] of D[32x128] = A[32x64] * B[64x128],
//   K channels: k=n -> (A=Px, B=Qr); k=32+n -> (A=-Py, B=Qi).
// 3xTF32 emulation: D += Ah*Bh + Ah*Bl + Al*Bh (error ~1e-6).
// m16n8k8 tiles: 2 m-tiles x 16 n-tiles x 8 k-steps; 8 warps, 2 n-tiles each.
// SMEM pitch 68 floats (68 mod 32 = 4): every fragment load and every
// prologue store is bank-conflict-free (bank = 4g+t+8ks, all distinct).

#define NTH 256
#define N2  32
#define TT  128
#define QP  68          // smem row pitch in floats

typedef unsigned int u32;

__device__ __forceinline__ float2 cmul(float2 a, float2 b) {
    return make_float2(a.x * b.x - a.y * b.y, a.x * b.y + a.y * b.x);
}
__device__ __forceinline__ u32 tf32_hi(float x) {
    u32 t; asm("cvt.rna.tf32.f32 %0, %1;" : "=r"(t) : "f"(x)); return t;
}
__device__ __forceinline__ void tf32_split(float x, u32& hi, u32& lo) {
    hi = tf32_hi(x);
    lo = tf32_hi(x - __uint_as_float(hi));
}
__device__ __forceinline__ void mma_tf32(float* c, const u32* a, const u32* b) {
    asm volatile(
        "mma.sync.aligned.m16n8k8.row.col.f32.tf32.tf32.f32 "
        "{%0,%1,%2,%3}, {%4,%5,%6,%7}, {%8,%9}, {%0,%1,%2,%3};"
        : "+f"(c[0]), "+f"(c[1]), "+f"(c[2]), "+f"(c[3])
        : "r"(a[0]), "r"(a[1]), "r"(a[2]), "r"(a[3]), "r"(b[0]), "r"(b[1]));
}

__global__ __launch_bounds__(NTH)
void s4d_mma_kernel(
    const float* __restrict__ log_dt,
    const float* __restrict__ C,          // (H, 32, 2)
    const float* __restrict__ lAr,        // (H, 32)
    const float* __restrict__ Aim,        // (H, 32)
    float* __restrict__ out,              // (H, L)
    int L)
{
    __shared__ float  sQ[TT * QP];        // [i][k] : k=n -> Qr, k=32+n -> Qi
    __shared__ float  sP[N2 * QP];        // [j][k] : k=n -> Px, k=32+n -> -Py
    __shared__ float2 sPow[N2 * 12];      // w^(2^k)
    __shared__ float2 sCcf[N2];

    const int h = blockIdx.x, tid = threadIdx.x;
    const int wid = tid >> 5, lane = tid & 31;
    const int g = lane >> 2, t = lane & 3;     // mma quad coords

    // ---------- Phase 0: per-n coefficients + power table ----------
    if (tid < N2) {
        const int n = tid, gg = h * N2 + n;
        float dt  = expf(log_dt[h]);
        float ar0 = -expf(lAr[gg]);
        float ai0 = Aim[gg];
        float e = expf(ar0 * dt), s, c;
        sincosf(ai0 * dt, &s, &c);
        float2 z = make_float2(e * c, e * s);      // w = exp(dtA)
        #pragma unroll
        for (int k = 0; k < 12; k++) {
            sPow[n * 12 + k] = z;
            z = make_float2(z.x * z.x - z.y * z.y, 2.0f * z.x * z.y);
        }
        float2 w0 = sPow[n * 12];
        float Er = w0.x - 1.0f, Ei = w0.y;
        float inv = 1.0f / (ar0 * ar0 + ai0 * ai0);
        float Dr = (Er * ar0 + Ei * ai0) * inv;
        float Di = (Ei * ar0 - Er * ai0) * inv;
        float cr = C[2 * gg], ci = C[2 * gg + 1];
        sCcf[n] = make_float2(2.0f * (cr * Dr - ci * Di),
                              2.0f * (cr * Di + ci * Dr));
    }
    __syncthreads();

    // ---------- Q: recurrence, thread (n=lane, seg=wid) covers i=16*seg.. ----------
    {
        const int n = lane, seg = wid;
        float2 z = sCcf[n];
        if (seg & 1) z = cmul(z, sPow[n * 12 + 4]);
        if (seg & 2) z = cmul(z, sPow[n * 12 + 5]);
        if (seg & 4) z = cmul(z, sPow[n * 12 + 6]);
        float2 w = sPow[n * 12];
        #pragma unroll
        for (int k = 0; k < 16; k++) {
            int i = seg * 16 + k;
            sQ[i * QP + n]      = z.x;   // Qr   (bank 4i+n: conflict-free)
            sQ[i * QP + n + 32] = z.y;   // Qi
            z = cmul(z, w);
        }
    }
    // ---------- P: w^(128j) via power table, thread (n, j) ----------
    #pragma unroll
    for (int r = 0; r < 4; r++) {
        int idx = r * NTH + tid;
        int n = idx & 31, j = idx >> 5;
        float2 z = make_float2(1.0f, 0.0f);
        if (j & 1)  z = cmul(z, sPow[n * 12 + 7]);
        if (j & 2)  z = cmul(z, sPow[n * 12 + 8]);
        if (j & 4)  z = cmul(z, sPow[n * 12 + 9]);
        if (j & 8)  z = cmul(z, sPow[n * 12 + 10]);
        if (j & 16) z = cmul(z, sPow[n * 12 + 11]);
        sP[j * QP + n]      = z.x;       // Px
        sP[j * QP + n + 32] = -z.y;      // -Py
    }
    __syncthreads();

    // ---------- Mainloop: warp w covers i in [16w, 16w+16), 2 n-tiles ----------
    float acc[2][2][4];
    #pragma unroll
    for (int mt = 0; mt < 2; mt++)
        #pragma unroll
        for (int nt = 0; nt < 2; nt++)
            #pragma unroll
            for (int c = 0; c < 4; c++) acc[mt][nt][c] = 0.0f;

    #pragma unroll
    for (int ks = 0; ks < 8; ks++) {
        const int kb = 8 * ks;
        // A fragments (P matrix, rows j), split hi/lo
        u32 ahi[2][4], alo[2][4];
        #pragma unroll
        for (int mt = 0; mt < 2; mt++) {
            float a0 = sP[(16 * mt + g)     * QP + kb + t];
            float a1 = sP[(16 * mt + g + 8) * QP + kb + t];
            float a2 = sP[(16 * mt + g)     * QP + kb + t + 4];
            float a3 = sP[(16 * mt + g + 8) * QP + kb + t + 4];
            tf32_split(a0, ahi[mt][0], alo[mt][0]);
            tf32_split(a1, ahi[mt][1], alo[mt][1]);
            tf32_split(a2, ahi[mt][2], alo[mt][2]);
            tf32_split(a3, ahi[mt][3], alo[mt][3]);
        }
        // B fragments (Q matrix, rows i = cols of B), split hi/lo
        u32 bhi[2][2], blo[2][2];
        #pragma unroll
        for (int nt = 0; nt < 2; nt++) {
            int ib = 16 * wid + 8 * nt;
            float b0 = sQ[(ib + g) * QP + kb + t];
            float b1 = sQ[(ib + g) * QP + kb + t + 4];
            tf32_split(b0, bhi[nt][0], blo[nt][0]);
            tf32_split(b1, bhi[nt][1], blo[nt][1]);
        }
        // 3xTF32: Ah*Bh, Ah*Bl, Al*Bh
        #pragma unroll
        for (int mt = 0; mt < 2; mt++)
            #pragma unroll
            for (int nt = 0; nt < 2; nt++)
                mma_tf32(acc[mt][nt], ahi[mt], bhi[nt]);
        #pragma unroll
        for (int mt = 0; mt < 2; mt++)
            #pragma unroll
            for (int nt = 0; nt < 2; nt++)
                mma_tf32(acc[mt][nt], ahi[mt], blo[nt]);
        #pragma unroll
        for (int mt = 0; mt < 2; mt++)
            #pragma unroll
            for (int nt = 0; nt < 2; nt++)
                mma_tf32(acc[mt][nt], alo[mt], bhi[nt]);
    }

    // ---------- Epilogue: D[j,i] -> out[h, j*128 + i], float2 stores ----------
    float* op = out + (size_t)h * (size_t)L;
    #pragma unroll
    for (int mt = 0; mt < 2; mt++) {
        #pragma unroll
        for (int nt = 0; nt < 2; nt++) {
            int j0 = 16 * mt + g;
            int i0 = 16 * wid + 8 * nt + 2 * t;
            *(float2*)&op[j0 * TT + i0]       = make_float2(acc[mt][nt][0], acc[mt][nt][1]);
            *(float2*)&op[(j0 + 8) * TT + i0] = make_float2(acc[mt][nt][2], acc[mt][nt][3]);
        }
    }
}

extern "C" void kernel_launch(void* const* d_in, const int* in_sizes, int n_in,
                              void* d_out, int out_size) {
    // inputs: [0]=L (scalar), [1]=log_dt (H), [2]=C (H,32,2),
    //         [3]=log_A_real (H,32), [4]=A_imag (H,32)
    const float* log_dt = (const float*)d_in[1];
    const float* C      = (const float*)d_in[2];
    const float* lAr    = (const float*)d_in[3];
    const float* Aim    = (const float*)d_in[4];
    float* out = (float*)d_out;

    int H = in_sizes[1];          // 1024
    int L = out_size / H;         // 4096

    s4d_mma_kernel<<<H, NTH>>>(log_dt, C, lAr, Aim, out, L);
}